// round 9
// baseline (speedup 1.0000x reference)
#include <cuda_runtime.h>

#define BB 8
#define TT 2048
#define CC 1024
#define HH 64
#define TOK (BB*TT)   // 16384

// scratch for q, k, v projections (device globals: allocation-guard-safe)
__device__ float g_q[TOK*HH];
__device__ float g_k[TOK*HH];
__device__ float g_v[TOK*HH];

// ---------------------------------------------------------------------------
// Fused QKV projection: for W in {Wq, Wk, Wv}:  out[16384,64] = x[16384,1024]@W
// 64-row tile per block, BK=16, 16x16 threads, each thread owns 4 rows x 4
// cols x 3 outputs. x tile loaded ONCE per k-step, used for all three GEMMs.
// ---------------------------------------------------------------------------
__global__ __launch_bounds__(256) void qkv_gemm_fused(const float* __restrict__ A,
                                                      const float* __restrict__ Wq,
                                                      const float* __restrict__ Wk,
                                                      const float* __restrict__ Wv) {
    __shared__ float As[64][17];      // pad: rows differing by 4 hit distinct banks
    __shared__ float Bs[3][16][64];   // q, k, v weight tiles

    const int t  = threadIdx.x;
    const int ty = t >> 4;            // 0..15
    const int tx = t & 15;            // 0..15
    const int rowbase = blockIdx.x * 64;

    float acc[3][4][4];
#pragma unroll
    for (int w = 0; w < 3; w++)
#pragma unroll
        for (int i = 0; i < 4; i++)
#pragma unroll
            for (int j = 0; j < 4; j++) acc[w][i][j] = 0.f;

    const float* Ws[3] = {Wq, Wk, Wv};

    for (int k0 = 0; k0 < CC; k0 += 16) {
        // A tile 64x16 (1024 floats): one float4 per thread
        {
            const int r  = t >> 2;          // 0..63
            const int cg = (t & 3) * 4;     // 0,4,8,12
            float4 va = *reinterpret_cast<const float4*>(
                &A[(size_t)(rowbase + r) * CC + k0 + cg]);
            As[r][cg + 0] = va.x; As[r][cg + 1] = va.y;
            As[r][cg + 2] = va.z; As[r][cg + 3] = va.w;
        }
        // three W tiles 16x64 each (1024 floats each): one float4 per thread per W
        {
            const int r  = t >> 4;          // 0..15
            const int cg = (t & 15) * 4;    // 0..60
#pragma unroll
            for (int w = 0; w < 3; w++) {
                float4 vb = *reinterpret_cast<const float4*>(
                    &Ws[w][(size_t)(k0 + r) * HH + cg]);
                *reinterpret_cast<float4*>(&Bs[w][r][cg]) = vb;
            }
        }
        __syncthreads();

#pragma unroll
        for (int kk = 0; kk < 16; kk++) {
            float a[4];
#pragma unroll
            for (int i = 0; i < 4; i++) a[i] = As[ty * 4 + i][kk];
#pragma unroll
            for (int w = 0; w < 3; w++) {
                float b[4];
#pragma unroll
                for (int j = 0; j < 4; j++) b[j] = Bs[w][kk][tx * 4 + j];
#pragma unroll
                for (int i = 0; i < 4; i++)
#pragma unroll
                    for (int j = 0; j < 4; j++)
                        acc[w][i][j] = fmaf(a[i], b[j], acc[w][i][j]);
            }
        }
        __syncthreads();
    }

    float* Os[3] = {g_q, g_k, g_v};
#pragma unroll
    for (int w = 0; w < 3; w++)
#pragma unroll
        for (int i = 0; i < 4; i++) {
            const int r = rowbase + ty * 4 + i;
#pragma unroll
            for (int j = 0; j < 4; j++)
                Os[w][(size_t)r * HH + tx * 4 + j] = acc[w][i][j];
        }
}

// ---------------------------------------------------------------------------
// Flash attention, causal. One CTA = 64-query tile of one batch.
// 16x16 threads, 4 rows x 4 cols per thread. d = 64.
// smem: Qs[64][64] natural, KP[64][64] (K transposed [d][key], then reused
// for P [row][key]), Vs[64][64] natural. Exactly 48 KB.
// K/V tiles are software-pipelined: tile kt+1 is prefetched into registers
// while tile kt is being consumed (grid is only ~1.7 CTAs/SM, so ILP — not
// occupancy — is the latency-hiding mechanism here).
// ---------------------------------------------------------------------------
__global__ __launch_bounds__(256) void attn_kernel(float* __restrict__ Out) {
    __shared__ float Qs[64][64];
    __shared__ float KP[64][64];
    __shared__ float Vs[64][64];

    const int t  = threadIdx.x;
    const int ty = t >> 4;
    const int tx = t & 15;
    const int qi = (int)(gridDim.x - 1 - blockIdx.x);  // reversed: big tiles first
    const int b  = blockIdx.y;

    // per-thread K/V slice coordinates (same for every tile)
    // rep r handles float4 #(r*256+t): key row = idx>>4, d-group = (idx&15)*4
    const float* Qb = g_q + ((size_t)b * TT + (size_t)qi * 64) * HH;

    // prefetch registers for the NEXT K/V tile
    float4 pk[4], pv[4];

    // prefetch tile 0 first so its latency overlaps the Q-tile load
    {
        const float* Kb = g_k + ((size_t)b * TT) * HH;
        const float* Vb = g_v + ((size_t)b * TT) * HH;
#pragma unroll
        for (int rep = 0; rep < 4; rep++) {
            const int idx = rep * 256 + t;
            const int key = idx >> 4;
            const int dg  = (idx & 15) * 4;
            pk[rep] = *reinterpret_cast<const float4*>(&Kb[(size_t)key * HH + dg]);
            pv[rep] = *reinterpret_cast<const float4*>(&Vb[(size_t)key * HH + dg]);
        }
    }

    // load Q tile (4096 floats, 4 x float4 per thread)
#pragma unroll
    for (int rep = 0; rep < 4; rep++) {
        const int idx = rep * 256 + t;     // float4 index 0..1023
        const int r   = idx >> 4;          // 0..63
        const int cg  = (idx & 15) * 4;    // 0..60
        *reinterpret_cast<float4*>(&Qs[r][cg]) =
            *reinterpret_cast<const float4*>(&Qb[(size_t)r * HH + cg]);
    }

    float m[4], l[4], o[4][4];
#pragma unroll
    for (int i = 0; i < 4; i++) {
        m[i] = -1e30f;
        l[i] = 0.f;
#pragma unroll
        for (int j = 0; j < 4; j++) o[i][j] = 0.f;
    }

    const float scale = 0.03125f;  // 1024^-0.5

    for (int kt = 0; kt <= qi; kt++) {
        __syncthreads();  // previous iteration's KP/Vs readers are done

        // publish prefetched K (transposed [d][key]) and V (natural [key][d])
#pragma unroll
        for (int rep = 0; rep < 4; rep++) {
            const int idx = rep * 256 + t;
            const int key = idx >> 4;          // 0..63
            const int dg  = (idx & 15) * 4;    // 0..60
            KP[dg + 0][key] = pk[rep].x; KP[dg + 1][key] = pk[rep].y;
            KP[dg + 2][key] = pk[rep].z; KP[dg + 3][key] = pk[rep].w;
            *reinterpret_cast<float4*>(&Vs[key][dg]) = pv[rep];
        }
        __syncthreads();

        // issue prefetch for tile kt+1; latency hides under S/softmax/PV below
        if (kt < qi) {
            const float* Kn = g_k + ((size_t)b * TT + (size_t)(kt + 1) * 64) * HH;
            const float* Vn = g_v + ((size_t)b * TT + (size_t)(kt + 1) * 64) * HH;
#pragma unroll
            for (int rep = 0; rep < 4; rep++) {
                const int idx = rep * 256 + t;
                const int key = idx >> 4;
                const int dg  = (idx & 15) * 4;
                pk[rep] = *reinterpret_cast<const float4*>(&Kn[(size_t)key * HH + dg]);
                pv[rep] = *reinterpret_cast<const float4*>(&Vn[(size_t)key * HH + dg]);
            }
        }

        // S = Q K^T (4x4 per thread)
        float s[4][4];
#pragma unroll
        for (int i = 0; i < 4; i++)
#pragma unroll
            for (int j = 0; j < 4; j++) s[i][j] = 0.f;

#pragma unroll 16
        for (int d = 0; d < 64; d++) {
            float a[4], bb[4];
#pragma unroll
            for (int i = 0; i < 4; i++) a[i] = Qs[ty * 4 + i][d];
#pragma unroll
            for (int j = 0; j < 4; j++) bb[j] = KP[d][tx * 4 + j];
#pragma unroll
            for (int i = 0; i < 4; i++)
#pragma unroll
                for (int j = 0; j < 4; j++)
                    s[i][j] = fmaf(a[i], bb[j], s[i][j]);
        }

        // scale + causal mask (only diagonal tile needs masking)
        if (kt == qi) {
#pragma unroll
            for (int i = 0; i < 4; i++) {
                const int qrow = ty * 4 + i;
#pragma unroll
                for (int j = 0; j < 4; j++) {
                    const int kcol = tx * 4 + j;
                    s[i][j] = (kcol > qrow) ? -1e30f : s[i][j] * scale;
                }
            }
        } else {
#pragma unroll
            for (int i = 0; i < 4; i++)
#pragma unroll
                for (int j = 0; j < 4; j++) s[i][j] *= scale;
        }

        // online softmax per owned row; row reduction across the 16 tx lanes
        float p[4][4];
#pragma unroll
        for (int i = 0; i < 4; i++) {
            float rmax = s[i][0];
#pragma unroll
            for (int j = 1; j < 4; j++) rmax = fmaxf(rmax, s[i][j]);
#pragma unroll
            for (int off = 8; off > 0; off >>= 1)
                rmax = fmaxf(rmax, __shfl_xor_sync(0xffffffffu, rmax, off));

            const float newm = fmaxf(m[i], rmax);
            const float corr = __expf(m[i] - newm);
            float rsum = 0.f;
#pragma unroll
            for (int j = 0; j < 4; j++) {
                p[i][j] = __expf(s[i][j] - newm);
                rsum += p[i][j];
            }
#pragma unroll
            for (int off = 8; off > 0; off >>= 1)
                rsum += __shfl_xor_sync(0xffffffffu, rsum, off);

            l[i] = l[i] * corr + rsum;
            m[i] = newm;
#pragma unroll
            for (int j = 0; j < 4; j++) o[i][j] *= corr;
        }

        __syncthreads();  // all threads done reading K half of KP

        // store P into KP ([row][key])
#pragma unroll
        for (int i = 0; i < 4; i++)
#pragma unroll
            for (int j = 0; j < 4; j++)
                KP[ty * 4 + i][tx * 4 + j] = p[i][j];
        __syncthreads();

        // O += P @ V
#pragma unroll 16
        for (int kk = 0; kk < 64; kk++) {
            float a[4], bb[4];
#pragma unroll
            for (int i = 0; i < 4; i++) a[i] = KP[ty * 4 + i][kk];
#pragma unroll
            for (int j = 0; j < 4; j++) bb[j] = Vs[kk][tx * 4 + j];
#pragma unroll
            for (int i = 0; i < 4; i++)
#pragma unroll
                for (int j = 0; j < 4; j++)
                    o[i][j] = fmaf(a[i], bb[j], o[i][j]);
        }
    }

    float* Ob = Out + ((size_t)b * TT + (size_t)qi * 64) * HH;
#pragma unroll
    for (int i = 0; i < 4; i++) {
        const float inv = 1.f / l[i];
#pragma unroll
        for (int j = 0; j < 4; j++)
            Ob[(size_t)(ty * 4 + i) * HH + tx * 4 + j] = o[i][j] * inv;
    }
}

// ---------------------------------------------------------------------------
// Launch. Inputs (metadata order): x, Wk, Wq, Wv. Output: [8,2048,64] f32.
// ---------------------------------------------------------------------------
extern "C" void kernel_launch(void* const* d_in, const int* in_sizes, int n_in,
                              void* d_out, int out_size) {
    const float* x  = (const float*)d_in[0];
    const float* Wk = (const float*)d_in[1];
    const float* Wq = (const float*)d_in[2];
    const float* Wv = (const float*)d_in[3];
    float* out = (float*)d_out;

    qkv_gemm_fused<<<TOK / 64, 256>>>(x, Wq, Wk, Wv);
    attn_kernel<<<dim3(TT / 64, BB), 256>>>(out);
}

// round 12
// speedup vs baseline: 1.2342x; 1.2342x over previous
#include <cuda_runtime.h>
#include <cuda_bf16.h>
#include <cstdint>

#define BB 8
#define TT 2048
#define CC 1024
#define HH 64
#define TOK (BB*TT)   // 16384

// scratch (device globals: allocation-guard-safe)
__device__ float g_q[TOK*HH];
__device__ float g_k[TOK*HH];
__device__ float g_v[TOK*HH];
// W transposed+split to bf16: [w(3)][s(hi/lo)][n(64)][k(1024)]
__device__ __nv_bfloat16 g_wt[3*2*64*1024];

// ---------------------------------------------------------------------------
// helpers
// ---------------------------------------------------------------------------
__device__ __forceinline__ uint32_t smem_u32(const void* p) {
    uint32_t a;
    asm("{ .reg .u64 t; cvta.to.shared.u64 t, %1; cvt.u32.u64 %0, t; }" : "=r"(a) : "l"(p));
    return a;
}

__device__ __forceinline__ void ldsm_x4(uint32_t* r, uint32_t addr) {
    asm volatile("ldmatrix.sync.aligned.m8n8.x4.shared.b16 {%0,%1,%2,%3}, [%4];"
        : "=r"(r[0]), "=r"(r[1]), "=r"(r[2]), "=r"(r[3]) : "r"(addr));
}
__device__ __forceinline__ void ldsm_x2(uint32_t* r, uint32_t addr) {
    asm volatile("ldmatrix.sync.aligned.m8n8.x2.shared.b16 {%0,%1}, [%2];"
        : "=r"(r[0]), "=r"(r[1]) : "r"(addr));
}
// D += A*B, bf16 inputs, fp32 accum (classic warp MMA — valid on plain sm_103)
__device__ __forceinline__ void mma_bf16(float* d, const uint32_t* a, const uint32_t* b) {
    asm volatile("mma.sync.aligned.m16n8k16.row.col.f32.bf16.bf16.f32 "
        "{%0,%1,%2,%3}, {%4,%5,%6,%7}, {%8,%9}, {%0,%1,%2,%3};"
        : "+f"(d[0]), "+f"(d[1]), "+f"(d[2]), "+f"(d[3])
        : "r"(a[0]), "r"(a[1]), "r"(a[2]), "r"(a[3]), "r"(b[0]), "r"(b[1]));
}

__device__ __forceinline__ void bf16_split(float x, __nv_bfloat16& hi, __nv_bfloat16& lo) {
    hi = __float2bfloat16(x);
    lo = __float2bfloat16(x - __bfloat162float(hi));   // x - hi exact in fp32
}

// ---------------------------------------------------------------------------
// Pre-kernel: transpose + hi/lo split W into g_wt[w][s][n][k]
// ---------------------------------------------------------------------------
__global__ void wsplit_kernel(const float* __restrict__ Wq,
                              const float* __restrict__ Wk,
                              const float* __restrict__ Wv) {
    const int idx = blockIdx.x * blockDim.x + threadIdx.x;   // over 3*64*1024
    if (idx >= 3 * 64 * 1024) return;
    const int w = idx >> 16;
    const int rem = idx & 65535;
    const int n = rem >> 10;
    const int k = rem & 1023;
    const float* W = (w == 0) ? Wq : (w == 1) ? Wk : Wv;
    __nv_bfloat16 hi, lo;
    bf16_split(W[(size_t)k * HH + n], hi, lo);
    g_wt[((size_t)(w * 2 + 0) * 64 + n) * 1024 + k] = hi;
    g_wt[((size_t)(w * 2 + 1) * 64 + n) * 1024 + k] = lo;
}

// ---------------------------------------------------------------------------
// QKV GEMM via mma.sync bf16 (hi/lo split, 3 terms, fp32 accum).
// CTA = 128 rows x 192 cols (q|k|v). 8 warps, each: 16 rows x 192 cols
// = 24 m16n8 accumulator tiles. K chunked by 64 into smem.
// smem rows padded to 72 bf16 (144B stride -> conflict-free ldmatrix).
//   XH [128][72] bf16 @0       (18432 B)
//   XL [128][72] bf16 @18432   (18432 B)
//   W  6 tiles [64][72] bf16 @36864 (6*9216 = 55296 B)   tile = w*2+s
// ---------------------------------------------------------------------------
#define XH_OFF 0
#define XL_OFF 18432
#define W_OFF  36864
#define QKV_SMEM 92160

__global__ __launch_bounds__(256) void qkv_mma_kernel(const float* __restrict__ X) {
    extern __shared__ char smem[];
    const int tid  = threadIdx.x;
    const int wid  = tid >> 5;
    const int lane = tid & 31;
    const int rowbase = blockIdx.x * 128;
    const uint32_t sb = smem_u32(smem);

    float acc[24][4];
#pragma unroll
    for (int i = 0; i < 24; i++)
#pragma unroll
        for (int j = 0; j < 4; j++) acc[i][j] = 0.f;

    // ldmatrix lane-address bases
    // A (m16k16 via x4): row = l&15, k-block = l>>4
    const uint32_t a_row = (uint32_t)(wid * 16 + (lane & 15));
    const uint32_t a_kb  = (uint32_t)(lane >> 4);
    const uint32_t aH_base = sb + XH_OFF + a_row * 144 + a_kb * 16;
    const uint32_t aL_base = sb + XL_OFF + a_row * 144 + a_kb * 16;
    // B (k16n8 via x2 on [n][k] tiles): n = l&7, k-block = (l>>3)&1
    const uint32_t b_n  = (uint32_t)(lane & 7);
    const uint32_t b_kb = (uint32_t)((lane >> 3) & 1);
    const uint32_t b_base = sb + W_OFF + b_n * 144 + b_kb * 16;

    for (int chunk = 0; chunk < 16; chunk++) {
        const int k0c = chunk * 64;

        // ---- x chunk [128 x 64] fp32 -> hi/lo bf16 into XH/XL
#pragma unroll
        for (int rep = 0; rep < 8; rep++) {
            const int fidx = rep * 256 + tid;       // 2048 float4 units
            const int r  = fidx >> 4;               // 0..127
            const int cg = (fidx & 15) * 4;         // 0..60
            float4 v = *reinterpret_cast<const float4*>(
                &X[(size_t)(rowbase + r) * CC + k0c + cg]);
            __nv_bfloat16 h0,l0,h1,l1,h2,l2,h3,l3;
            bf16_split(v.x, h0, l0); bf16_split(v.y, h1, l1);
            bf16_split(v.z, h2, l2); bf16_split(v.w, h3, l3);
            uint32_t hi01 = ((uint32_t)__bfloat16_as_ushort(h1) << 16) | __bfloat16_as_ushort(h0);
            uint32_t hi23 = ((uint32_t)__bfloat16_as_ushort(h3) << 16) | __bfloat16_as_ushort(h2);
            uint32_t lo01 = ((uint32_t)__bfloat16_as_ushort(l1) << 16) | __bfloat16_as_ushort(l0);
            uint32_t lo23 = ((uint32_t)__bfloat16_as_ushort(l3) << 16) | __bfloat16_as_ushort(l2);
            const uint32_t boff = (uint32_t)(r * 144 + cg * 2);
            *reinterpret_cast<uint2*>(smem + XH_OFF + boff) = make_uint2(hi01, hi23);
            *reinterpret_cast<uint2*>(smem + XL_OFF + boff) = make_uint2(lo01, lo23);
        }

        // ---- W tiles: 6 x [64 rows x 64 k] bf16 from g_wt
#pragma unroll
        for (int rep = 0; rep < 12; rep++) {
            const int u = rep * 256 + tid;          // 0..3071 (16B units)
            const int tile = u >> 9;                // /512
            const int rn = (u >> 3) & 63;
            const int kq = u & 7;
            uint4 val = *reinterpret_cast<const uint4*>(
                &g_wt[((size_t)tile * 64 + rn) * 1024 + k0c + kq * 8]);
            *reinterpret_cast<uint4*>(smem + W_OFF + tile * 9216 + rn * 144 + kq * 16) = val;
        }
        __syncthreads();

        // ---- 4 k16 steps x 24 tiles x 3 split terms
#pragma unroll
        for (int ks = 0; ks < 4; ks++) {
            uint32_t ah[4], al[4];
            ldsm_x4(ah, aH_base + ks * 32);
            ldsm_x4(al, aL_base + ks * 32);
#pragma unroll
            for (int w3 = 0; w3 < 3; w3++) {
#pragma unroll
                for (int nt = 0; nt < 8; nt++) {
                    uint32_t bh[2], bl[2];
                    const uint32_t baddrH = b_base + (w3 * 2) * 9216 + nt * 8 * 144 + ks * 32;
                    ldsm_x2(bh, baddrH);
                    ldsm_x2(bl, baddrH + 9216);
                    float* c = acc[w3 * 8 + nt];
                    mma_bf16(c, ah, bh);
                    mma_bf16(c, ah, bl);
                    mma_bf16(c, al, bh);
                }
            }
        }
        __syncthreads();
    }

    // ---- epilogue: write q/k/v (fragment c0,c1 -> row g; c2,c3 -> row g+8)
    float* const outs[3] = {g_q, g_k, g_v};
    const int g = lane >> 2, t4 = lane & 3;
#pragma unroll
    for (int w3 = 0; w3 < 3; w3++) {
#pragma unroll
        for (int nt = 0; nt < 8; nt++) {
            float* c = acc[w3 * 8 + nt];
            const int col = nt * 8 + t4 * 2;
            const size_t r0 = (size_t)(rowbase + wid * 16 + g);
            *reinterpret_cast<float2*>(&outs[w3][r0 * HH + col]) = make_float2(c[0], c[1]);
            *reinterpret_cast<float2*>(&outs[w3][(r0 + 8) * HH + col]) = make_float2(c[2], c[3]);
        }
    }
}

// ---------------------------------------------------------------------------
// Flash attention, causal (unchanged: measured 297us, fp32).
// ---------------------------------------------------------------------------
__global__ __launch_bounds__(256) void attn_kernel(float* __restrict__ Out) {
    __shared__ float Qs[64][64];
    __shared__ float KP[64][64];
    __shared__ float Vs[64][64];

    const int t  = threadIdx.x;
    const int ty = t >> 4;
    const int tx = t & 15;
    const int qi = (int)(gridDim.x - 1 - blockIdx.x);
    const int b  = blockIdx.y;

    const float* Qb = g_q + ((size_t)b * TT + (size_t)qi * 64) * HH;

    float4 pk[4], pv[4];
    {
        const float* Kb = g_k + ((size_t)b * TT) * HH;
        const float* Vb = g_v + ((size_t)b * TT) * HH;
#pragma unroll
        for (int rep = 0; rep < 4; rep++) {
            const int idx = rep * 256 + t;
            const int key = idx >> 4;
            const int dg  = (idx & 15) * 4;
            pk[rep] = *reinterpret_cast<const float4*>(&Kb[(size_t)key * HH + dg]);
            pv[rep] = *reinterpret_cast<const float4*>(&Vb[(size_t)key * HH + dg]);
        }
    }

#pragma unroll
    for (int rep = 0; rep < 4; rep++) {
        const int idx = rep * 256 + t;
        const int r   = idx >> 4;
        const int cg  = (idx & 15) * 4;
        *reinterpret_cast<float4*>(&Qs[r][cg]) =
            *reinterpret_cast<const float4*>(&Qb[(size_t)r * HH + cg]);
    }

    float m[4], l[4], o[4][4];
#pragma unroll
    for (int i = 0; i < 4; i++) {
        m[i] = -1e30f; l[i] = 0.f;
#pragma unroll
        for (int j = 0; j < 4; j++) o[i][j] = 0.f;
    }

    const float scale = 0.03125f;

    for (int kt = 0; kt <= qi; kt++) {
        __syncthreads();
#pragma unroll
        for (int rep = 0; rep < 4; rep++) {
            const int idx = rep * 256 + t;
            const int key = idx >> 4;
            const int dg  = (idx & 15) * 4;
            KP[dg + 0][key] = pk[rep].x; KP[dg + 1][key] = pk[rep].y;
            KP[dg + 2][key] = pk[rep].z; KP[dg + 3][key] = pk[rep].w;
            *reinterpret_cast<float4*>(&Vs[key][dg]) = pv[rep];
        }
        __syncthreads();

        if (kt < qi) {
            const float* Kn = g_k + ((size_t)b * TT + (size_t)(kt + 1) * 64) * HH;
            const float* Vn = g_v + ((size_t)b * TT + (size_t)(kt + 1) * 64) * HH;
#pragma unroll
            for (int rep = 0; rep < 4; rep++) {
                const int idx = rep * 256 + t;
                const int key = idx >> 4;
                const int dg  = (idx & 15) * 4;
                pk[rep] = *reinterpret_cast<const float4*>(&Kn[(size_t)key * HH + dg]);
                pv[rep] = *reinterpret_cast<const float4*>(&Vn[(size_t)key * HH + dg]);
            }
        }

        float s[4][4];
#pragma unroll
        for (int i = 0; i < 4; i++)
#pragma unroll
            for (int j = 0; j < 4; j++) s[i][j] = 0.f;

#pragma unroll 16
        for (int d = 0; d < 64; d++) {
            float a[4], bb[4];
#pragma unroll
            for (int i = 0; i < 4; i++) a[i] = Qs[ty * 4 + i][d];
#pragma unroll
            for (int j = 0; j < 4; j++) bb[j] = KP[d][tx * 4 + j];
#pragma unroll
            for (int i = 0; i < 4; i++)
#pragma unroll
                for (int j = 0; j < 4; j++)
                    s[i][j] = fmaf(a[i], bb[j], s[i][j]);
        }

        if (kt == qi) {
#pragma unroll
            for (int i = 0; i < 4; i++) {
                const int qrow = ty * 4 + i;
#pragma unroll
                for (int j = 0; j < 4; j++) {
                    const int kcol = tx * 4 + j;
                    s[i][j] = (kcol > qrow) ? -1e30f : s[i][j] * scale;
                }
            }
        } else {
#pragma unroll
            for (int i = 0; i < 4; i++)
#pragma unroll
                for (int j = 0; j < 4; j++) s[i][j] *= scale;
        }

        float p[4][4];
#pragma unroll
        for (int i = 0; i < 4; i++) {
            float rmax = s[i][0];
#pragma unroll
            for (int j = 1; j < 4; j++) rmax = fmaxf(rmax, s[i][j]);
#pragma unroll
            for (int off = 8; off > 0; off >>= 1)
                rmax = fmaxf(rmax, __shfl_xor_sync(0xffffffffu, rmax, off));

            const float newm = fmaxf(m[i], rmax);
            const float corr = __expf(m[i] - newm);
            float rsum = 0.f;
#pragma unroll
            for (int j = 0; j < 4; j++) {
                p[i][j] = __expf(s[i][j] - newm);
                rsum += p[i][j];
            }
#pragma unroll
            for (int off = 8; off > 0; off >>= 1)
                rsum += __shfl_xor_sync(0xffffffffu, rsum, off);

            l[i] = l[i] * corr + rsum;
            m[i] = newm;
#pragma unroll
            for (int j = 0; j < 4; j++) o[i][j] *= corr;
        }

        __syncthreads();
#pragma unroll
        for (int i = 0; i < 4; i++)
#pragma unroll
            for (int j = 0; j < 4; j++)
                KP[ty * 4 + i][tx * 4 + j] = p[i][j];
        __syncthreads();

#pragma unroll 16
        for (int kk = 0; kk < 64; kk++) {
            float a[4], bb[4];
#pragma unroll
            for (int i = 0; i < 4; i++) a[i] = KP[ty * 4 + i][kk];
#pragma unroll
            for (int j = 0; j < 4; j++) bb[j] = Vs[kk][tx * 4 + j];
#pragma unroll
            for (int i = 0; i < 4; i++)
#pragma unroll
                for (int j = 0; j < 4; j++)
                    o[i][j] = fmaf(a[i], bb[j], o[i][j]);
        }
    }

    float* Ob = Out + ((size_t)b * TT + (size_t)qi * 64) * HH;
#pragma unroll
    for (int i = 0; i < 4; i++) {
        const float inv = 1.f / l[i];
#pragma unroll
        for (int j = 0; j < 4; j++)
            Ob[(size_t)(ty * 4 + i) * HH + tx * 4 + j] = o[i][j] * inv;
    }
}

// ---------------------------------------------------------------------------
// Launch. Inputs (metadata order): x, Wk, Wq, Wv. Output: [8,2048,64] f32.
// ---------------------------------------------------------------------------
extern "C" void kernel_launch(void* const* d_in, const int* in_sizes, int n_in,
                              void* d_out, int out_size) {
    const float* x  = (const float*)d_in[0];
    const float* Wk = (const float*)d_in[1];
    const float* Wq = (const float*)d_in[2];
    const float* Wv = (const float*)d_in[3];
    float* out = (float*)d_out;

    static int smem_set = 0;
    if (!smem_set) {
        cudaFuncSetAttribute(qkv_mma_kernel,
                             cudaFuncAttributeMaxDynamicSharedMemorySize, QKV_SMEM);
        smem_set = 1;
    }

    wsplit_kernel<<<(3 * 64 * 1024 + 255) / 256, 256>>>(Wq, Wk, Wv);
    qkv_mma_kernel<<<TOK / 128, 256, QKV_SMEM>>>(x);
    attn_kernel<<<dim3(TT / 64, BB), 256>>>(out);
}

// round 15
// speedup vs baseline: 2.7698x; 2.2443x over previous
#include <cuda_runtime.h>
#include <cuda_bf16.h>
#include <cstdint>

#define BB 8
#define TT 2048
#define CC 1024
#define HH 64
#define TOK (BB*TT)   // 16384

// bf16 hi/lo intermediates (q pre-scaled by 1024^-0.5)
__device__ __nv_bfloat16 g_qh[TOK*HH], g_ql[TOK*HH];
__device__ __nv_bfloat16 g_kh[TOK*HH], g_kl[TOK*HH];
__device__ __nv_bfloat16 g_vh[TOK*HH], g_vl[TOK*HH];
// W transposed+split to bf16: [w(3)][s(hi/lo)][n(64)][k(1024)]
__device__ __nv_bfloat16 g_wt[3*2*64*1024];

// ---------------------------------------------------------------------------
// helpers
// ---------------------------------------------------------------------------
__device__ __forceinline__ uint32_t smem_u32(const void* p) {
    uint32_t a;
    asm("{ .reg .u64 t; cvta.to.shared.u64 t, %1; cvt.u32.u64 %0, t; }" : "=r"(a) : "l"(p));
    return a;
}
__device__ __forceinline__ void ldsm_x4(uint32_t* r, uint32_t addr) {
    asm volatile("ldmatrix.sync.aligned.m8n8.x4.shared.b16 {%0,%1,%2,%3}, [%4];"
        : "=r"(r[0]), "=r"(r[1]), "=r"(r[2]), "=r"(r[3]) : "r"(addr));
}
__device__ __forceinline__ void ldsm_x2(uint32_t* r, uint32_t addr) {
    asm volatile("ldmatrix.sync.aligned.m8n8.x2.shared.b16 {%0,%1}, [%2];"
        : "=r"(r[0]), "=r"(r[1]) : "r"(addr));
}
__device__ __forceinline__ void ldsm_x2_trans(uint32_t* r, uint32_t addr) {
    asm volatile("ldmatrix.sync.aligned.m8n8.x2.trans.shared.b16 {%0,%1}, [%2];"
        : "=r"(r[0]), "=r"(r[1]) : "r"(addr));
}
__device__ __forceinline__ void mma_bf16(float* d, const uint32_t* a, const uint32_t* b) {
    asm volatile("mma.sync.aligned.m16n8k16.row.col.f32.bf16.bf16.f32 "
        "{%0,%1,%2,%3}, {%4,%5,%6,%7}, {%8,%9}, {%0,%1,%2,%3};"
        : "+f"(d[0]), "+f"(d[1]), "+f"(d[2]), "+f"(d[3])
        : "r"(a[0]), "r"(a[1]), "r"(a[2]), "r"(a[3]), "r"(b[0]), "r"(b[1]));
}
__device__ __forceinline__ void bf16_split(float x, __nv_bfloat16& hi, __nv_bfloat16& lo) {
    hi = __float2bfloat16(x);
    lo = __float2bfloat16(x - __bfloat162float(hi));
}
// pack (a,b) -> {lo16=a, hi16=b} for hi; same for residuals
__device__ __forceinline__ void split2(float a, float b, uint32_t& hi, uint32_t& lo) {
    __nv_bfloat16 ah = __float2bfloat16(a), bh = __float2bfloat16(b);
    hi = ((uint32_t)__bfloat16_as_ushort(bh) << 16) | __bfloat16_as_ushort(ah);
    float al = a - __bfloat162float(ah);
    float bl = b - __bfloat162float(bh);
    __nv_bfloat16 alh = __float2bfloat16(al), blh = __float2bfloat16(bl);
    lo = ((uint32_t)__bfloat16_as_ushort(blh) << 16) | __bfloat16_as_ushort(alh);
}

// ---------------------------------------------------------------------------
// Pre-kernel: transpose + hi/lo split W into g_wt[w][s][n][k]
// ---------------------------------------------------------------------------
__global__ void wsplit_kernel(const float* __restrict__ Wq,
                              const float* __restrict__ Wk,
                              const float* __restrict__ Wv) {
    const int idx = blockIdx.x * blockDim.x + threadIdx.x;
    if (idx >= 3 * 64 * 1024) return;
    const int w = idx >> 16;
    const int rem = idx & 65535;
    const int n = rem >> 10;
    const int k = rem & 1023;
    const float* W = (w == 0) ? Wq : (w == 1) ? Wk : Wv;
    __nv_bfloat16 hi, lo;
    bf16_split(W[(size_t)k * HH + n], hi, lo);
    g_wt[((size_t)(w * 2 + 0) * 64 + n) * 1024 + k] = hi;
    g_wt[((size_t)(w * 2 + 1) * 64 + n) * 1024 + k] = lo;
}

// ---------------------------------------------------------------------------
// QKV GEMM via mma.sync bf16 (validated R12). Epilogue emits bf16 hi/lo
// (q pre-scaled by 0.03125) instead of fp32.
// ---------------------------------------------------------------------------
#define XH_OFF 0
#define XL_OFF 18432
#define W_OFF  36864
#define QKV_SMEM 92160

__global__ __launch_bounds__(256) void qkv_mma_kernel(const float* __restrict__ X) {
    extern __shared__ char smem[];
    const int tid  = threadIdx.x;
    const int wid  = tid >> 5;
    const int lane = tid & 31;
    const int rowbase = blockIdx.x * 128;
    const uint32_t sb = smem_u32(smem);

    float acc[24][4];
#pragma unroll
    for (int i = 0; i < 24; i++)
#pragma unroll
        for (int j = 0; j < 4; j++) acc[i][j] = 0.f;

    const uint32_t a_row = (uint32_t)(wid * 16 + (lane & 15));
    const uint32_t a_kb  = (uint32_t)(lane >> 4);
    const uint32_t aH_base = sb + XH_OFF + a_row * 144 + a_kb * 16;
    const uint32_t aL_base = sb + XL_OFF + a_row * 144 + a_kb * 16;
    const uint32_t b_n  = (uint32_t)(lane & 7);
    const uint32_t b_kb = (uint32_t)((lane >> 3) & 1);
    const uint32_t b_base = sb + W_OFF + b_n * 144 + b_kb * 16;

    for (int chunk = 0; chunk < 16; chunk++) {
        const int k0c = chunk * 64;
#pragma unroll
        for (int rep = 0; rep < 8; rep++) {
            const int fidx = rep * 256 + tid;
            const int r  = fidx >> 4;
            const int cg = (fidx & 15) * 4;
            float4 v = *reinterpret_cast<const float4*>(
                &X[(size_t)(rowbase + r) * CC + k0c + cg]);
            uint32_t hi01, lo01, hi23, lo23;
            split2(v.x, v.y, hi01, lo01);
            split2(v.z, v.w, hi23, lo23);
            const uint32_t boff = (uint32_t)(r * 144 + cg * 2);
            *reinterpret_cast<uint2*>(smem + XH_OFF + boff) = make_uint2(hi01, hi23);
            *reinterpret_cast<uint2*>(smem + XL_OFF + boff) = make_uint2(lo01, lo23);
        }
#pragma unroll
        for (int rep = 0; rep < 12; rep++) {
            const int u = rep * 256 + tid;
            const int tile = u >> 9;
            const int rn = (u >> 3) & 63;
            const int kq = u & 7;
            uint4 val = *reinterpret_cast<const uint4*>(
                &g_wt[((size_t)tile * 64 + rn) * 1024 + k0c + kq * 8]);
            *reinterpret_cast<uint4*>(smem + W_OFF + tile * 9216 + rn * 144 + kq * 16) = val;
        }
        __syncthreads();

#pragma unroll
        for (int ks = 0; ks < 4; ks++) {
            uint32_t ah[4], al[4];
            ldsm_x4(ah, aH_base + ks * 32);
            ldsm_x4(al, aL_base + ks * 32);
#pragma unroll
            for (int w3 = 0; w3 < 3; w3++) {
#pragma unroll
                for (int nt = 0; nt < 8; nt++) {
                    uint32_t bh[2], bl[2];
                    const uint32_t baddrH = b_base + (w3 * 2) * 9216 + nt * 8 * 144 + ks * 32;
                    ldsm_x2(bh, baddrH);
                    ldsm_x2(bl, baddrH + 9216);
                    float* c = acc[w3 * 8 + nt];
                    mma_bf16(c, ah, bh);
                    mma_bf16(c, ah, bl);
                    mma_bf16(c, al, bh);
                }
            }
        }
        __syncthreads();
    }

    // epilogue: hi/lo bf16 outputs; q scaled by 1024^-0.5
    __nv_bfloat16* const oh[3] = {g_qh, g_kh, g_vh};
    __nv_bfloat16* const ol[3] = {g_ql, g_kl, g_vl};
    const int g = lane >> 2, t4 = lane & 3;
#pragma unroll
    for (int w3 = 0; w3 < 3; w3++) {
        const float sc = (w3 == 0) ? 0.03125f : 1.0f;
#pragma unroll
        for (int nt = 0; nt < 8; nt++) {
            float* c = acc[w3 * 8 + nt];
            uint32_t h01, l01, h23, l23;
            split2(c[0] * sc, c[1] * sc, h01, l01);
            split2(c[2] * sc, c[3] * sc, h23, l23);
            const int col = nt * 8 + t4 * 2;
            const size_t r0 = (size_t)(rowbase + wid * 16 + g);
            *reinterpret_cast<uint32_t*>(&oh[w3][r0 * HH + col]) = h01;
            *reinterpret_cast<uint32_t*>(&ol[w3][r0 * HH + col]) = l01;
            *reinterpret_cast<uint32_t*>(&oh[w3][(r0 + 8) * HH + col]) = h23;
            *reinterpret_cast<uint32_t*>(&ol[w3][(r0 + 8) * HH + col]) = l23;
        }
    }
}

// ---------------------------------------------------------------------------
// Flash attention on mma.sync. CTA = 64 queries (4 warps x 16 rows), k-tiles
// of 64 keys. S = QhKh+QhKl+QlKh; P,V hi/lo split: PhVh+PhVl+PlVh.
// P stays in registers (C-fragment == A-fragment layout). V B-operand via
// ldmatrix.trans on natural [key][d] layout. smem rows padded to 144B.
// ---------------------------------------------------------------------------
#define AT_QH 0
#define AT_QL 9216
#define AT_KH 18432
#define AT_KL 27648
#define AT_VH 36864
#define AT_VL 46080
#define ATTN_SMEM 55296

__global__ __launch_bounds__(128) void attn_mma_kernel(float* __restrict__ Out) {
    extern __shared__ char sm[];
    const uint32_t sb = smem_u32(sm);
    const int tid = threadIdx.x;
    const int wid = tid >> 5;
    const int lane = tid & 31;
    const int g = lane >> 2, t4 = lane & 3;
    const int qi = (int)(gridDim.x - 1 - blockIdx.x);   // big tiles first
    const int b  = blockIdx.y;

    // copy Q (pre-scaled, split) into smem
    {
        const __nv_bfloat16* Qh = g_qh + ((size_t)b * TT + qi * 64) * HH;
        const __nv_bfloat16* Ql = g_ql + ((size_t)b * TT + qi * 64) * HH;
#pragma unroll
        for (int rep = 0; rep < 4; rep++) {
            const int u = rep * 128 + tid;      // 512 uint4 per array
            const int r = u >> 3, c8 = u & 7;
            const size_t go = (size_t)r * HH + c8 * 8;
            const uint32_t so = r * 144 + c8 * 16;
            *reinterpret_cast<uint4*>(sm + AT_QH + so) =
                *reinterpret_cast<const uint4*>(Qh + go);
            *reinterpret_cast<uint4*>(sm + AT_QL + so) =
                *reinterpret_cast<const uint4*>(Ql + go);
        }
    }

    const uint32_t qh_base = sb + AT_QH + (wid * 16 + (lane & 15)) * 144 + (lane >> 4) * 16;
    const uint32_t ql_base = qh_base + (AT_QL - AT_QH);
    const uint32_t kh_base = sb + AT_KH + (lane & 7) * 144 + ((lane >> 3) & 1) * 16;
    const uint32_t vh_base = sb + AT_VH + (lane & 15) * 144;

    float o[8][4];
#pragma unroll
    for (int i = 0; i < 8; i++)
#pragma unroll
        for (int j = 0; j < 4; j++) o[i][j] = 0.f;
    float m0 = -1e30f, m1 = -1e30f, l0 = 0.f, l1 = 0.f;

    for (int kt = 0; kt <= qi; kt++) {
        __syncthreads();   // previous tile's consumers done
        {
            const size_t base = ((size_t)b * TT + kt * 64) * HH;
            const __nv_bfloat16* Kh = g_kh + base;
            const __nv_bfloat16* Kl = g_kl + base;
            const __nv_bfloat16* Vh = g_vh + base;
            const __nv_bfloat16* Vl = g_vl + base;
#pragma unroll
            for (int rep = 0; rep < 4; rep++) {
                const int u = rep * 128 + tid;
                const int r = u >> 3, c8 = u & 7;
                const size_t go = (size_t)r * HH + c8 * 8;
                const uint32_t so = r * 144 + c8 * 16;
                *reinterpret_cast<uint4*>(sm + AT_KH + so) = *reinterpret_cast<const uint4*>(Kh + go);
                *reinterpret_cast<uint4*>(sm + AT_KL + so) = *reinterpret_cast<const uint4*>(Kl + go);
                *reinterpret_cast<uint4*>(sm + AT_VH + so) = *reinterpret_cast<const uint4*>(Vh + go);
                *reinterpret_cast<uint4*>(sm + AT_VL + so) = *reinterpret_cast<const uint4*>(Vl + go);
            }
        }
        __syncthreads();

        // ---- S = Q K^T
        float s[8][4];
#pragma unroll
        for (int i = 0; i < 8; i++)
#pragma unroll
            for (int j = 0; j < 4; j++) s[i][j] = 0.f;

#pragma unroll
        for (int ks = 0; ks < 4; ks++) {
            uint32_t qh[4], ql[4];
            ldsm_x4(qh, qh_base + ks * 32);
            ldsm_x4(ql, ql_base + ks * 32);
#pragma unroll
            for (int nt = 0; nt < 8; nt++) {
                uint32_t kh2[2], kl2[2];
                const uint32_t ka = kh_base + nt * 1152 + ks * 32;
                ldsm_x2(kh2, ka);
                ldsm_x2(kl2, ka + 9216);
                mma_bf16(s[nt], qh, kh2);
                mma_bf16(s[nt], qh, kl2);
                mma_bf16(s[nt], ql, kh2);
            }
        }

        // ---- causal mask (diagonal tile only)
        if (kt == qi) {
            const int r0 = wid * 16 + g, r1 = r0 + 8;
#pragma unroll
            for (int nt = 0; nt < 8; nt++) {
                const int c0 = nt * 8 + 2 * t4;
                if (c0     > r0) s[nt][0] = -1e30f;
                if (c0 + 1 > r0) s[nt][1] = -1e30f;
                if (c0     > r1) s[nt][2] = -1e30f;
                if (c0 + 1 > r1) s[nt][3] = -1e30f;
            }
        }

        // ---- online softmax (rows g / g+8; quad = one row's 4 lanes)
        float rx0 = -1e30f, rx1 = -1e30f;
#pragma unroll
        for (int nt = 0; nt < 8; nt++) {
            rx0 = fmaxf(rx0, fmaxf(s[nt][0], s[nt][1]));
            rx1 = fmaxf(rx1, fmaxf(s[nt][2], s[nt][3]));
        }
        rx0 = fmaxf(rx0, __shfl_xor_sync(0xffffffffu, rx0, 1));
        rx0 = fmaxf(rx0, __shfl_xor_sync(0xffffffffu, rx0, 2));
        rx1 = fmaxf(rx1, __shfl_xor_sync(0xffffffffu, rx1, 1));
        rx1 = fmaxf(rx1, __shfl_xor_sync(0xffffffffu, rx1, 2));
        const float nm0 = fmaxf(m0, rx0), nm1 = fmaxf(m1, rx1);
        const float cf0 = __expf(m0 - nm0), cf1 = __expf(m1 - nm1);
        m0 = nm0; m1 = nm1;

        float rs0 = 0.f, rs1 = 0.f;
#pragma unroll
        for (int nt = 0; nt < 8; nt++) {
            s[nt][0] = __expf(s[nt][0] - nm0);
            s[nt][1] = __expf(s[nt][1] - nm0);
            s[nt][2] = __expf(s[nt][2] - nm1);
            s[nt][3] = __expf(s[nt][3] - nm1);
            rs0 += s[nt][0] + s[nt][1];
            rs1 += s[nt][2] + s[nt][3];
        }
        rs0 += __shfl_xor_sync(0xffffffffu, rs0, 1);
        rs0 += __shfl_xor_sync(0xffffffffu, rs0, 2);
        rs1 += __shfl_xor_sync(0xffffffffu, rs1, 1);
        rs1 += __shfl_xor_sync(0xffffffffu, rs1, 2);
        l0 = l0 * cf0 + rs0;
        l1 = l1 * cf1 + rs1;
#pragma unroll
        for (int nt = 0; nt < 8; nt++) {
            o[nt][0] *= cf0; o[nt][1] *= cf0;
            o[nt][2] *= cf1; o[nt][3] *= cf1;
        }

        // ---- pack P fragments (hi/lo) in registers
        uint32_t ph[4][4], pl[4][4];
#pragma unroll
        for (int kg = 0; kg < 4; kg++) {
            const int te = 2 * kg, to = 2 * kg + 1;
            split2(s[te][0], s[te][1], ph[kg][0], pl[kg][0]);
            split2(s[te][2], s[te][3], ph[kg][1], pl[kg][1]);
            split2(s[to][0], s[to][1], ph[kg][2], pl[kg][2]);
            split2(s[to][2], s[to][3], ph[kg][3], pl[kg][3]);
        }

        // ---- O += P V  (V via ldmatrix.trans on [key][d])
#pragma unroll
        for (int kg = 0; kg < 4; kg++) {
#pragma unroll
            for (int dt = 0; dt < 8; dt++) {
                uint32_t vh2[2], vl2[2];
                const uint32_t va = vh_base + kg * 2304 + dt * 16;
                ldsm_x2_trans(vh2, va);
                ldsm_x2_trans(vl2, va + 9216);
                mma_bf16(o[dt], ph[kg], vh2);
                mma_bf16(o[dt], ph[kg], vl2);
                mma_bf16(o[dt], pl[kg], vh2);
            }
        }
    }

    // ---- final normalize + store
    const float i0 = 1.f / l0, i1 = 1.f / l1;
    const size_t row0 = (size_t)b * TT + qi * 64 + wid * 16 + g;
#pragma unroll
    for (int nt = 0; nt < 8; nt++) {
        const int col = nt * 8 + 2 * t4;
        *reinterpret_cast<float2*>(&Out[row0 * HH + col]) =
            make_float2(o[nt][0] * i0, o[nt][1] * i0);
        *reinterpret_cast<float2*>(&Out[(row0 + 8) * HH + col]) =
            make_float2(o[nt][2] * i1, o[nt][3] * i1);
    }
}

// ---------------------------------------------------------------------------
// Launch. Inputs (metadata order): x, Wk, Wq, Wv. Output: [8,2048,64] f32.
// ---------------------------------------------------------------------------
extern "C" void kernel_launch(void* const* d_in, const int* in_sizes, int n_in,
                              void* d_out, int out_size) {
    const float* x  = (const float*)d_in[0];
    const float* Wk = (const float*)d_in[1];
    const float* Wq = (const float*)d_in[2];
    const float* Wv = (const float*)d_in[3];
    float* out = (float*)d_out;

    static int smem_set = 0;
    if (!smem_set) {
        cudaFuncSetAttribute(qkv_mma_kernel,
                             cudaFuncAttributeMaxDynamicSharedMemorySize, QKV_SMEM);
        cudaFuncSetAttribute(attn_mma_kernel,
                             cudaFuncAttributeMaxDynamicSharedMemorySize, ATTN_SMEM);
        smem_set = 1;
    }

    wsplit_kernel<<<(3 * 64 * 1024 + 255) / 256, 256>>>(Wq, Wk, Wv);
    qkv_mma_kernel<<<TOK / 128, 256, QKV_SMEM>>>(x);
    attn_mma_kernel<<<dim3(TT / 64, BB), 128, ATTN_SMEM>>>(out);
}